// round 2
// baseline (speedup 1.0000x reference)
#include <cuda_runtime.h>

#define NTOT 32768
#define TPB  1024

// Soft-shrinkage gate: sigmoid(10(y-b)) + sigmoid(-10(y+b))
// With u = exp(-10y), E = exp(10b):
//   s1 = 1/(1+uE), s2 = u/(u+E)
//   s1+s2 = (u^2 E + 2u + E) / ((1+uE)(u+E))   -> 1 EX2 + 1 RCP
__device__ __forceinline__ float gate_fn(float y, float E) {
    float a = -10.0f * y;
    a = fminf(fmaxf(a, -40.0f), 40.0f);   // clamp: keeps u^2*E finite; error ~e^-37 in saturation
    float u  = __expf(a);
    float t1 = u * E;
    float num = fmaf(u, t1, fmaf(2.0f, u, E));   // u^2 E + 2u + E
    float den = (t1 + 1.0f) * (u + E);
    return __fdividef(num, den);
}

// Boundary path for analysis: y[ch,m] = sum_t K[ch,t] * c[2m+t-3], zero outside [0,M)
__device__ __noinline__ float2 ana_edge(const float* __restrict__ c,
                                        const float* __restrict__ k8,
                                        int m0, int M) {
    float y0 = 0.0f, y1 = 0.0f;
#pragma unroll
    for (int t = 0; t < 8; t++) {
        float kv = k8[t];
        int p0 = 2 * m0 + t - 3;
        if (p0 >= 0 && p0 < M) y0 = fmaf(kv, c[p0], y0);
        int p1 = p0 + 2;
        if (p1 >= 0 && p1 < M) y1 = fmaf(kv, c[p1], y1);
    }
    return make_float2(y0, y1);
}

// Boundary path for synthesis:
// out[g,p] = sum_{r,s: (p+3-s) even, m=(p+3-s)/2 in [0,H)} y[2g+r,m] * K[2g+r,s]
__device__ __noinline__ float2 syn_edge(const float* __restrict__ sm,
                                        const float* __restrict__ kf,
                                        int g, int h0, int HS) {
    int H = 1 << HS;
    float o0 = 0.0f, o1 = 0.0f;
#pragma unroll
    for (int r = 0; r < 2; r++) {
        const float* c  = sm + ((2 * g + r) << HS);
        const float* k8 = kf + (2 * g + r) * 8;
#pragma unroll
        for (int i = 0; i < 4; i++) {
            int m = h0 + 1 - i;                 // s = 2i+1
            if (m >= 0 && m < H)  o0 = fmaf(k8[2 * i + 1], c[m], o0);
            int m2 = h0 + 2 - i;                // s = 2i
            if (m2 >= 0 && m2 < H) o1 = fmaf(k8[2 * i], c[m2], o1);
        }
    }
    return make_float2(o0, o1);
}

// Analysis level LVL: input G=2^LVL channels x M, output 2G channels x M/2 (in place).
// Layout: channel ch at linear offset ch*len; total is always 32768 floats.
template<int LVL>
__device__ void analysis_stage(float* sm, const float* kf, const float* Et) {
    const int HS = 14 - LVL;     // log2 of output channel length H = M/2
    const int MS = 15 - LVL;     // log2 of input channel length M
    const int H  = 1 << HS;
    const int M  = 1 << MS;
    const int tid = threadIdx.x;
    float acc[32];
#pragma unroll
    for (int j = 0; j < 16; j++) {
        int q  = tid + j * TPB;          // pair index
        int e0 = q << 1;                 // output linear index (even)
        int ch = e0 >> HS;
        int m0 = e0 & (H - 1);           // even since H >= 1024
        int g  = ch >> 1;
        const float* cbase = sm + (g << MS);
        float4 K0 = *(const float4*)(kf + ch * 8);
        float4 K1 = *(const float4*)(kf + ch * 8 + 4);
        float y0, y1;
        if (m0 >= 2 && m0 <= H - 4) {
            const float* p = cbase + (m0 << 1);      // 16B aligned (m0 even)
            float4 A  = *(const float4*)(p - 4);     // w[0..3]  = c[2m0-4 .. 2m0-1]
            float4 Bv = *(const float4*)(p);         // w[4..7]
            float4 Cv = *(const float4*)(p + 4);     // w[8..11]
            // y0 taps w[1..8], y1 taps w[3..10]
            y0 =      K0.x * A.y;
            y0 = fmaf(K0.y, A.z,  y0);
            y0 = fmaf(K0.z, A.w,  y0);
            y0 = fmaf(K0.w, Bv.x, y0);
            y0 = fmaf(K1.x, Bv.y, y0);
            y0 = fmaf(K1.y, Bv.z, y0);
            y0 = fmaf(K1.z, Bv.w, y0);
            y0 = fmaf(K1.w, Cv.x, y0);
            y1 =      K0.x * A.w;
            y1 = fmaf(K0.y, Bv.x, y1);
            y1 = fmaf(K0.z, Bv.y, y1);
            y1 = fmaf(K0.w, Bv.z, y1);
            y1 = fmaf(K1.x, Bv.w, y1);
            y1 = fmaf(K1.y, Cv.x, y1);
            y1 = fmaf(K1.z, Cv.y, y1);
            y1 = fmaf(K1.w, Cv.z, y1);
        } else {
            float2 rr = ana_edge(cbase, kf + ch * 8, m0, M);
            y0 = rr.x; y1 = rr.y;
        }
        float E = Et[ch];
        acc[2 * j]     = y0 * gate_fn(y0, E);
        acc[2 * j + 1] = y1 * gate_fn(y1, E);
    }
    __syncthreads();   // all reads done before in-place overwrite
#pragma unroll
    for (int j = 0; j < 16; j++) {
        int q = tid + j * TPB;
        *(float2*)(sm + (q << 1)) = make_float2(acc[2 * j], acc[2 * j + 1]);
    }
    __syncthreads();
}

// Synthesis level LVL: input 2G channels x H, output G channels x M=2H (in place).
template<int LVL>
__device__ void synthesis_stage(float* sm, const float* kf) {
    const int MS = 15 - LVL;
    const int HS = 14 - LVL;
    const int H  = 1 << HS;
    const int M  = 1 << MS;
    const int tid = threadIdx.x;
    float acc[32];
#pragma unroll
    for (int j = 0; j < 16; j++) {
        int q  = tid + j * TPB;
        int e0 = q << 1;
        int g  = e0 >> MS;
        int p0 = e0 & (M - 1);    // even
        int h0 = p0 >> 1;
        float o0, o1;
        if (h0 >= 2 && h0 <= H - 3) {
            const float* c0 = sm + (g << MS) + h0;   // channel 2g
            const float* c1 = c0 + H;                // channel 2g+1
            float4 Ka = *(const float4*)(kf + g * 16);       // K[2g][0..3]
            float4 Kb = *(const float4*)(kf + g * 16 + 4);   // K[2g][4..7]
            float4 Kc = *(const float4*)(kf + g * 16 + 8);   // K[2g+1][0..3]
            float4 Kd = *(const float4*)(kf + g * 16 + 12);  // K[2g+1][4..7]
            float am2 = c0[-2], am1 = c0[-1], a0 = c0[0], a1 = c0[1], a2 = c0[2];
            float bm2 = c1[-2], bm1 = c1[-1], b0 = c1[0], b1 = c1[1], b2 = c1[2];
            // o0 (p even): taps k1*v[h0+1] + k3*v[h0] + k5*v[h0-1] + k7*v[h0-2]
            o0 =      Ka.y * a1;
            o0 = fmaf(Ka.w, a0,  o0);
            o0 = fmaf(Kb.y, am1, o0);
            o0 = fmaf(Kb.w, am2, o0);
            o0 = fmaf(Kc.y, b1,  o0);
            o0 = fmaf(Kc.w, b0,  o0);
            o0 = fmaf(Kd.y, bm1, o0);
            o0 = fmaf(Kd.w, bm2, o0);
            // o1 (p odd): taps k0*v[h0+2] + k2*v[h0+1] + k4*v[h0] + k6*v[h0-1]
            o1 =      Ka.x * a2;
            o1 = fmaf(Ka.z, a1,  o1);
            o1 = fmaf(Kb.x, a0,  o1);
            o1 = fmaf(Kb.z, am1, o1);
            o1 = fmaf(Kc.x, b2,  o1);
            o1 = fmaf(Kc.z, b1,  o1);
            o1 = fmaf(Kd.x, b0,  o1);
            o1 = fmaf(Kd.z, bm1, o1);
        } else {
            float2 rr = syn_edge(sm, kf, g, h0, HS);
            o0 = rr.x; o1 = rr.y;
        }
        acc[2 * j]     = o0;
        acc[2 * j + 1] = o1;
    }
    __syncthreads();
#pragma unroll
    for (int j = 0; j < 16; j++) {
        int q = tid + j * TPB;
        *(float2*)(sm + (q << 1)) = make_float2(acc[2 * j], acc[2 * j + 1]);
    }
    __syncthreads();
}

__global__ void __launch_bounds__(TPB, 1)
wpt_kernel(const float* __restrict__ x,
           const float* __restrict__ k1, const float* __restrict__ k2,
           const float* __restrict__ k3, const float* __restrict__ k4,
           const float* __restrict__ k5,
           const float* __restrict__ b1, const float* __restrict__ b2,
           const float* __restrict__ b3, const float* __restrict__ b4,
           const float* __restrict__ b5,
           float* __restrict__ out)
{
    extern __shared__ float smem[];
    float* sm = smem;               // 32768 floats: the row
    float* kf = smem + NTOT;        // up to 32 rows x 8 taps
    float* Et = kf + 256;           // up to 32 channel exp(10b)
    const int tid = threadIdx.x;

    const float* xr   = x   + (size_t)blockIdx.x * NTOT;
    float*       orow = out + (size_t)blockIdx.x * NTOT;

#pragma unroll
    for (int i = tid; i < NTOT / 4; i += TPB)
        ((float4*)sm)[i] = ((const float4*)xr)[i];
    __syncthreads();

#define LOAD_TABLES(CH, KP, BP)                                          \
    do {                                                                 \
        if (tid < (CH) * 8) kf[tid] = (KP)[tid];                         \
        if (tid < (CH))     Et[tid] = __expf(10.0f * (BP)[tid]);         \
        __syncthreads();                                                 \
    } while (0)

#define LOAD_K(CH, KP)                                                   \
    do {                                                                 \
        if (tid < (CH) * 8) kf[tid] = (KP)[tid];                         \
        __syncthreads();                                                 \
    } while (0)

    // ---- Analysis ----
    LOAD_TABLES(2,  k1, b1);  analysis_stage<0>(sm, kf, Et);
    LOAD_TABLES(4,  k2, b2);  analysis_stage<1>(sm, kf, Et);
    LOAD_TABLES(8,  k3, b3);  analysis_stage<2>(sm, kf, Et);
    LOAD_TABLES(16, k4, b4);  analysis_stage<3>(sm, kf, Et);
    LOAD_TABLES(32, k5, b5);  analysis_stage<4>(sm, kf, Et);

    // ---- Synthesis ---- (kf already holds k5 after last analysis)
    synthesis_stage<4>(sm, kf);
    LOAD_K(16, k4);  synthesis_stage<3>(sm, kf);
    LOAD_K(8,  k3);  synthesis_stage<2>(sm, kf);
    LOAD_K(4,  k2);  synthesis_stage<1>(sm, kf);
    LOAD_K(2,  k1);  synthesis_stage<0>(sm, kf);

#pragma unroll
    for (int i = tid; i < NTOT / 4; i += TPB)
        ((float4*)orow)[i] = ((const float4*)sm)[i];

#undef LOAD_TABLES
#undef LOAD_K
}

extern "C" void kernel_launch(void* const* d_in, const int* in_sizes, int n_in,
                              void* d_out, int out_size) {
    const float* x  = (const float*)d_in[0];
    const float* k1 = (const float*)d_in[1];
    const float* k2 = (const float*)d_in[2];
    const float* k3 = (const float*)d_in[3];
    const float* k4 = (const float*)d_in[4];
    const float* k5 = (const float*)d_in[5];
    const float* b1 = (const float*)d_in[6];
    const float* b2 = (const float*)d_in[7];
    const float* b3 = (const float*)d_in[8];
    const float* b4 = (const float*)d_in[9];
    const float* b5 = (const float*)d_in[10];
    float* out = (float*)d_out;

    int nrows = out_size / NTOT;   // 128
    size_t smem_bytes = (size_t)(NTOT + 256 + 64) * sizeof(float);
    cudaFuncSetAttribute(wpt_kernel, cudaFuncAttributeMaxDynamicSharedMemorySize,
                         (int)smem_bytes);
    wpt_kernel<<<nrows, TPB, smem_bytes>>>(x, k1, k2, k3, k4, k5,
                                           b1, b2, b3, b4, b5, out);
}

// round 3
// speedup vs baseline: 1.0769x; 1.0769x over previous
#include <cuda_runtime.h>

#define NTOT 32768
#define TPB  1024

// Soft-shrinkage gate: sigmoid(10(y-b)) + sigmoid(-10(y+b))
// With u = exp(-10y), E = exp(10b):
//   s1+s2 = (u^2 E + 2u + E) / ((1+uE)(u+E))   -> 1 EX2 + 1 RCP
__device__ __forceinline__ float gate_fn(float y, float E) {
    float a = -10.0f * y;
    a = fminf(fmaxf(a, -40.0f), 40.0f);
    float u  = __expf(a);
    float t1 = u * E;
    float num = fmaf(u, t1, fmaf(2.0f, u, E));
    float den = (t1 + 1.0f) * (u + E);
    return __fdividef(num, den);
}

// Scalar edge path, analysis: 4 outputs m0..m0+3, taps c[2m+t-3] zero outside [0,M)
__device__ __noinline__ void ana_edge4(const float* __restrict__ c,
                                       const float* __restrict__ k8,
                                       int m0, int M, float* y) {
#pragma unroll
    for (int i = 0; i < 4; i++) {
        float s = 0.0f;
#pragma unroll
        for (int t = 0; t < 8; t++) {
            int p = 2 * (m0 + i) + t - 3;
            if (p >= 0 && p < M) s = fmaf(k8[t], c[p], s);
        }
        y[i] = s;
    }
}

// Scalar edge path, synthesis: 4 outputs p0..p0+3 of group g
__device__ __noinline__ void syn_edge4(const float* __restrict__ sm,
                                       const float* __restrict__ kf,
                                       int g, int p0, int HS, float* o) {
    int H = 1 << HS;
#pragma unroll
    for (int i = 0; i < 4; i++) {
        int p = p0 + i, h = p >> 1, odd = p & 1;
        float s = 0.0f;
#pragma unroll
        for (int r = 0; r < 2; r++) {
            const float* c  = sm + ((2 * g + r) << HS);
            const float* k8 = kf + (2 * g + r) * 8;
            if (odd) {
#pragma unroll
                for (int t = 0; t < 4; t++) {
                    int m = h + 2 - t;
                    if (m >= 0 && m < H) s = fmaf(k8[2 * t], c[m], s);
                }
            } else {
#pragma unroll
                for (int t = 0; t < 4; t++) {
                    int m = h + 1 - t;
                    if (m >= 0 && m < H) s = fmaf(k8[2 * t + 1], c[m], s);
                }
            }
        }
        o[i] = s;
    }
}

// Analysis level LVL: G=2^LVL channels x M -> 2G channels x H=M/2, in place.
template<int LVL>
__device__ void analysis_stage(float* sm, const float* kfl, const float* Etl) {
    const int HS = 14 - LVL;
    const int MS = 15 - LVL;
    const int H  = 1 << HS;
    const int M  = 1 << MS;
    const int tid = threadIdx.x;
    float4 acc[8];
#pragma unroll
    for (int j = 0; j < 8; j++) {
        int q  = tid + j * TPB;
        int e0 = q << 2;                 // output linear index, mult of 4
        int ch = e0 >> HS;
        int m0 = e0 & (H - 1);           // mult of 4
        int g  = ch >> 1;
        const float* cb = sm + (g << MS);
        float4 K0 = *(const float4*)(kfl + ch * 8);
        float4 K1 = *(const float4*)(kfl + ch * 8 + 4);
        float y0, y1, y2, y3;
        if (m0 >= 2 && m0 <= H - 6) {
            const float* pp = cb + (m0 << 1);          // mult of 8 -> 16B aligned
            float4 A  = *(const float4*)(pp - 4);      // c[2m0-4 .. 2m0-1]
            float4 Bv = *(const float4*)(pp);
            float4 Cv = *(const float4*)(pp + 4);
            float4 Dv = *(const float4*)(pp + 8);
            // w[u] = c[2m0-3+u];  A.y=w0.. D.z=w13
            y0 =      K0.x * A.y;
            y0 = fmaf(K0.y, A.z,  y0);  y0 = fmaf(K0.z, A.w,  y0);
            y0 = fmaf(K0.w, Bv.x, y0);  y0 = fmaf(K1.x, Bv.y, y0);
            y0 = fmaf(K1.y, Bv.z, y0);  y0 = fmaf(K1.z, Bv.w, y0);
            y0 = fmaf(K1.w, Cv.x, y0);
            y1 =      K0.x * A.w;
            y1 = fmaf(K0.y, Bv.x, y1);  y1 = fmaf(K0.z, Bv.y, y1);
            y1 = fmaf(K0.w, Bv.z, y1);  y1 = fmaf(K1.x, Bv.w, y1);
            y1 = fmaf(K1.y, Cv.x, y1);  y1 = fmaf(K1.z, Cv.y, y1);
            y1 = fmaf(K1.w, Cv.z, y1);
            y2 =      K0.x * Bv.y;
            y2 = fmaf(K0.y, Bv.z, y2);  y2 = fmaf(K0.z, Bv.w, y2);
            y2 = fmaf(K0.w, Cv.x, y2);  y2 = fmaf(K1.x, Cv.y, y2);
            y2 = fmaf(K1.y, Cv.z, y2);  y2 = fmaf(K1.z, Cv.w, y2);
            y2 = fmaf(K1.w, Dv.x, y2);
            y3 =      K0.x * Bv.w;
            y3 = fmaf(K0.y, Cv.x, y3);  y3 = fmaf(K0.z, Cv.y, y3);
            y3 = fmaf(K0.w, Cv.z, y3);  y3 = fmaf(K1.x, Cv.w, y3);
            y3 = fmaf(K1.y, Dv.x, y3);  y3 = fmaf(K1.z, Dv.y, y3);
            y3 = fmaf(K1.w, Dv.z, y3);
        } else {
            float yy[4];
            ana_edge4(cb, kfl + ch * 8, m0, M, yy);
            y0 = yy[0]; y1 = yy[1]; y2 = yy[2]; y3 = yy[3];
        }
        float E = Etl[ch];
        acc[j] = make_float4(y0 * gate_fn(y0, E), y1 * gate_fn(y1, E),
                             y2 * gate_fn(y2, E), y3 * gate_fn(y3, E));
    }
    __syncthreads();
#pragma unroll
    for (int j = 0; j < 8; j++)
        *(float4*)(sm + ((tid + j * TPB) << 2)) = acc[j];
    __syncthreads();
}

// Synthesis level LVL: 2G channels x H -> G channels x M=2H, in place.
template<int LVL>
__device__ void synthesis_stage(float* sm, const float* kfl) {
    const int MS = 15 - LVL;
    const int HS = 14 - LVL;
    const int H  = 1 << HS;
    const int M  = 1 << MS;
    const int tid = threadIdx.x;
    float4 acc[8];
#pragma unroll
    for (int j = 0; j < 8; j++) {
        int q  = tid + j * TPB;
        int e0 = q << 2;
        int g  = e0 >> MS;
        int p0 = e0 & (M - 1);           // mult of 4
        int h0 = p0 >> 1;                // even
        float4 Ka = *(const float4*)(kfl + g * 16);       // K[2g][0..3]
        float4 Kb = *(const float4*)(kfl + g * 16 + 4);   // K[2g][4..7]
        float4 Kc = *(const float4*)(kfl + g * 16 + 8);   // K[2g+1][0..3]
        float4 Kd = *(const float4*)(kfl + g * 16 + 12);  // K[2g+1][4..7]
        float o0, o1, o2, o3;
        if (h0 >= 2 && h0 <= H - 4) {
            const float* c0 = sm + (g << MS) + h0;   // channel 2g
            const float* c1 = c0 + H;                // channel 2g+1
            float2 aA = *(const float2*)(c0 - 2);    // a0=c0[h0-2], a1
            float2 aB = *(const float2*)(c0);        // a2, a3
            float2 aC = *(const float2*)(c0 + 2);    // a4, a5
            float2 bA = *(const float2*)(c1 - 2);
            float2 bB = *(const float2*)(c1);
            float2 bC = *(const float2*)(c1 + 2);
            // o(p even,h): k1*c[h+1]+k3*c[h]+k5*c[h-1]+k7*c[h-2]
            // o(p odd ,h): k0*c[h+2]+k2*c[h+1]+k4*c[h]+k6*c[h-1]
            o0 =      Ka.y * aB.y;
            o0 = fmaf(Ka.w, aB.x, o0);  o0 = fmaf(Kb.y, aA.y, o0);
            o0 = fmaf(Kb.w, aA.x, o0);  o0 = fmaf(Kc.y, bB.y, o0);
            o0 = fmaf(Kc.w, bB.x, o0);  o0 = fmaf(Kd.y, bA.y, o0);
            o0 = fmaf(Kd.w, bA.x, o0);
            o1 =      Ka.x * aC.x;
            o1 = fmaf(Ka.z, aB.y, o1);  o1 = fmaf(Kb.x, aB.x, o1);
            o1 = fmaf(Kb.z, aA.y, o1);  o1 = fmaf(Kc.x, bC.x, o1);
            o1 = fmaf(Kc.z, bB.y, o1);  o1 = fmaf(Kd.x, bB.x, o1);
            o1 = fmaf(Kd.z, bA.y, o1);
            o2 =      Ka.y * aC.x;
            o2 = fmaf(Ka.w, aB.y, o2);  o2 = fmaf(Kb.y, aB.x, o2);
            o2 = fmaf(Kb.w, aA.y, o2);  o2 = fmaf(Kc.y, bC.x, o2);
            o2 = fmaf(Kc.w, bB.y, o2);  o2 = fmaf(Kd.y, bB.x, o2);
            o2 = fmaf(Kd.w, bA.y, o2);
            o3 =      Ka.x * aC.y;
            o3 = fmaf(Ka.z, aC.x, o3);  o3 = fmaf(Kb.x, aB.y, o3);
            o3 = fmaf(Kb.z, aB.x, o3);  o3 = fmaf(Kc.x, bC.y, o3);
            o3 = fmaf(Kc.z, bC.x, o3);  o3 = fmaf(Kd.x, bB.y, o3);
            o3 = fmaf(Kd.z, bB.x, o3);
        } else {
            float oo[4];
            syn_edge4(sm, kfl, g, p0, HS, oo);
            o0 = oo[0]; o1 = oo[1]; o2 = oo[2]; o3 = oo[3];
        }
        acc[j] = make_float4(o0, o1, o2, o3);
    }
    __syncthreads();
#pragma unroll
    for (int j = 0; j < 8; j++)
        *(float4*)(sm + ((tid + j * TPB) << 2)) = acc[j];
    __syncthreads();
}

// Table layout (all levels resident): level l kernels at KOFF(l)= (1<<(l+1))*8-16,
// Et at EOFF(l) = (1<<(l+1))-2. Totals: 496 + 62 floats.
#define KOFF(l) (((1 << ((l) + 1)) * 8) - 16)
#define EOFF(l) ((1 << ((l) + 1)) - 2)

__global__ void __launch_bounds__(TPB, 1)
wpt_kernel(const float* __restrict__ x,
           const float* __restrict__ k1, const float* __restrict__ k2,
           const float* __restrict__ k3, const float* __restrict__ k4,
           const float* __restrict__ k5,
           const float* __restrict__ b1, const float* __restrict__ b2,
           const float* __restrict__ b3, const float* __restrict__ b4,
           const float* __restrict__ b5,
           float* __restrict__ out)
{
    extern __shared__ float smem[];
    float* sm = smem;               // 32768 floats: the row
    float* kf = smem + NTOT;        // 496 floats: all filter tables
    float* Et = kf + 496;           // 62 floats: all exp(10b)
    const int tid = threadIdx.x;

    const float* xr   = x   + (size_t)blockIdx.x * NTOT;
    float*       orow = out + (size_t)blockIdx.x * NTOT;

#pragma unroll
    for (int i = tid; i < NTOT / 4; i += TPB)
        ((float4*)sm)[i] = ((const float4*)xr)[i];

    // preload all tables once
    if (tid < 496) {
        float v;
        if      (tid < 16)  v = k1[tid];
        else if (tid < 48)  v = k2[tid - 16];
        else if (tid < 112) v = k3[tid - 48];
        else if (tid < 240) v = k4[tid - 112];
        else                v = k5[tid - 240];
        kf[tid] = v;
    } else if (tid >= 512 && tid < 574) {
        int u = tid - 512;
        float bv;
        if      (u < 2)  bv = b1[u];
        else if (u < 6)  bv = b2[u - 2];
        else if (u < 14) bv = b3[u - 6];
        else if (u < 30) bv = b4[u - 14];
        else             bv = b5[u - 30];
        Et[u] = __expf(10.0f * bv);
    }
    __syncthreads();

    // ---- Analysis ----
    analysis_stage<0>(sm, kf + KOFF(0), Et + EOFF(0));
    analysis_stage<1>(sm, kf + KOFF(1), Et + EOFF(1));
    analysis_stage<2>(sm, kf + KOFF(2), Et + EOFF(2));
    analysis_stage<3>(sm, kf + KOFF(3), Et + EOFF(3));
    analysis_stage<4>(sm, kf + KOFF(4), Et + EOFF(4));

    // ---- Synthesis ----
    synthesis_stage<4>(sm, kf + KOFF(4));
    synthesis_stage<3>(sm, kf + KOFF(3));
    synthesis_stage<2>(sm, kf + KOFF(2));
    synthesis_stage<1>(sm, kf + KOFF(1));
    synthesis_stage<0>(sm, kf + KOFF(0));

#pragma unroll
    for (int i = tid; i < NTOT / 4; i += TPB)
        ((float4*)orow)[i] = ((const float4*)sm)[i];
}

extern "C" void kernel_launch(void* const* d_in, const int* in_sizes, int n_in,
                              void* d_out, int out_size) {
    const float* x  = (const float*)d_in[0];
    const float* k1 = (const float*)d_in[1];
    const float* k2 = (const float*)d_in[2];
    const float* k3 = (const float*)d_in[3];
    const float* k4 = (const float*)d_in[4];
    const float* k5 = (const float*)d_in[5];
    const float* b1 = (const float*)d_in[6];
    const float* b2 = (const float*)d_in[7];
    const float* b3 = (const float*)d_in[8];
    const float* b4 = (const float*)d_in[9];
    const float* b5 = (const float*)d_in[10];
    float* out = (float*)d_out;

    int nrows = out_size / NTOT;   // 128
    size_t smem_bytes = (size_t)(NTOT + 496 + 62 + 32) * sizeof(float);
    cudaFuncSetAttribute(wpt_kernel, cudaFuncAttributeMaxDynamicSharedMemorySize,
                         (int)smem_bytes);
    wpt_kernel<<<nrows, TPB, smem_bytes>>>(x, k1, k2, k3, k4, k5,
                                           b1, b2, b3, b4, b5, out);
}